// round 1
// baseline (speedup 1.0000x reference)
#include <cuda_runtime.h>

#define NCLS   128
#define DIM    2048
#define NPTS   4096
#define CAP    512        // max rows per class (mean 32, 512 is absurdly safe)
#define KSPLIT 32
#define KCHUNK (DIM / KSPLIT)   // 64
#define PAIRS  (NCLS * NCLS)

// ---------------- scratch (device globals: no allocation allowed) ----------------
__device__ int    g_cnt[NCLS];
__device__ int    g_idx[NCLS * CAP];
__device__ float  g_meanR[NCLS * DIM];
__device__ float  g_meanT[NCLS * DIM];
__device__ float  g_meanC[NCLS * DIM];
__device__ float  g_nR[NCLS * 4];      // per-chunk partial squared norms
__device__ float  g_nT[NCLS * 4];
__device__ float  g_nC[NCLS * 4];
__device__ float  g_S1p[KSPLIT * PAIRS];   // split-K partial dots meanR . meanC
__device__ float  g_S2p[KSPLIT * PAIRS];   // split-K partial dots meanT . meanC
__device__ double g_blk[NCLS];             // per-block loss partials

// ---------------- kernel 1: zero counters ----------------
__global__ void k_zero() {
    int t = threadIdx.x;
    if (t < NCLS) g_cnt[t] = 0;
}

// ---------------- kernel 2: scatter row indices by class ----------------
__global__ void k_scatter(const int* __restrict__ tg) {
    int i = blockIdx.x * blockDim.x + threadIdx.x;
    if (i < NPTS) {
        int t = tg[i];
        int p = atomicAdd(&g_cnt[t], 1);
        g_idx[t * CAP + p] = i;
    }
}

// ---------------- kernel 3: segment means + norms ----------------
// grid: 512 blocks = 128 classes x 4 column chunks; 128 threads; thread owns 1 float4
__global__ void k_means(const float* __restrict__ m1, const float* __restrict__ m2) {
    int c  = blockIdx.x >> 2;
    int ch = blockIdx.x & 3;
    int off = ch * 512 + threadIdx.x * 4;

    int n = g_cnt[c];
    const int* il = g_idx + c * CAP;

    float4 aR = make_float4(0.f, 0.f, 0.f, 0.f);
    float4 aT = make_float4(0.f, 0.f, 0.f, 0.f);

    int j = 0;
    for (; j + 2 <= n; j += 2) {
        int i0 = il[j], i1 = il[j + 1];
        float4 r0 = *(const float4*)(m1 + i0 * DIM + off);
        float4 r1 = *(const float4*)(m1 + i1 * DIM + off);
        float4 t0 = *(const float4*)(m2 + i0 * DIM + off);
        float4 t1 = *(const float4*)(m2 + i1 * DIM + off);
        aR.x += r0.x + r1.x; aR.y += r0.y + r1.y; aR.z += r0.z + r1.z; aR.w += r0.w + r1.w;
        aT.x += t0.x + t1.x; aT.y += t0.y + t1.y; aT.z += t0.z + t1.z; aT.w += t0.w + t1.w;
    }
    if (j < n) {
        int i0 = il[j];
        float4 r0 = *(const float4*)(m1 + i0 * DIM + off);
        float4 t0 = *(const float4*)(m2 + i0 * DIM + off);
        aR.x += r0.x; aR.y += r0.y; aR.z += r0.z; aR.w += r0.w;
        aT.x += t0.x; aT.y += t0.y; aT.z += t0.z; aT.w += t0.w;
    }

    float inv = 1.f / (float)max(n, 1);
    float4 mR = make_float4(aR.x * inv, aR.y * inv, aR.z * inv, aR.w * inv);
    float4 mT = make_float4(aT.x * inv, aT.y * inv, aT.z * inv, aT.w * inv);
    float4 mC = make_float4(0.5f * (mR.x + mT.x), 0.5f * (mR.y + mT.y),
                            0.5f * (mR.z + mT.z), 0.5f * (mR.w + mT.w));

    int wb = c * DIM + off;
    *(float4*)(g_meanR + wb) = mR;
    *(float4*)(g_meanT + wb) = mT;
    *(float4*)(g_meanC + wb) = mC;

    // partial squared norms over this chunk
    float sR = mR.x*mR.x + mR.y*mR.y + mR.z*mR.z + mR.w*mR.w;
    float sT = mT.x*mT.x + mT.y*mT.y + mT.z*mT.z + mT.w*mT.w;
    float sC = mC.x*mC.x + mC.y*mC.y + mC.z*mC.z + mC.w*mC.w;

    #pragma unroll
    for (int o = 16; o > 0; o >>= 1) {
        sR += __shfl_down_sync(0xffffffffu, sR, o);
        sT += __shfl_down_sync(0xffffffffu, sT, o);
        sC += __shfl_down_sync(0xffffffffu, sC, o);
    }
    __shared__ float shn[3][4];
    int warp = threadIdx.x >> 5, lane = threadIdx.x & 31;
    if (lane == 0) { shn[0][warp] = sR; shn[1][warp] = sT; shn[2][warp] = sC; }
    __syncthreads();
    if (threadIdx.x == 0) {
        g_nR[c * 4 + ch] = shn[0][0] + shn[0][1] + shn[0][2] + shn[0][3];
        g_nT[c * 4 + ch] = shn[1][0] + shn[1][1] + shn[1][2] + shn[1][3];
        g_nC[c * 4 + ch] = shn[2][0] + shn[2][1] + shn[2][2] + shn[2][3];
    }
}

// ---------------- kernel 4: split-K GEMMs S1 = R*C^T, S2 = T*C^T ----------------
// grid: 128 blocks = 32 K-splits x (2x2 output tiles of 64x64); 256 threads; 4x4 reg tile
__global__ void k_gemm() {
    __shared__ float Rs[16][68];
    __shared__ float Ts[16][68];
    __shared__ float Cs[16][68];

    int bx = blockIdx.x;
    int ks = bx >> 2;
    int tile = bx & 3;
    int aBase = (tile >> 1) * 64;
    int bBase = (tile & 1) * 64;

    int tid = threadIdx.x;
    int tx = tid & 15;       // b direction
    int ty = tid >> 4;       // a direction

    int la = tid >> 2;            // 0..63 : row within tile for loads
    int lk = (tid & 3) * 4;       // 0,4,8,12 : k offset for loads

    float acc1[4][4] = {};
    float acc2[4][4] = {};

    int k0 = ks * KCHUNK;
    for (int kb = k0; kb < k0 + KCHUNK; kb += 16) {
        float4 vr = *(const float4*)(g_meanR + (aBase + la) * DIM + kb + lk);
        float4 vt = *(const float4*)(g_meanT + (aBase + la) * DIM + kb + lk);
        float4 vc = *(const float4*)(g_meanC + (bBase + la) * DIM + kb + lk);
        __syncthreads();
        Rs[lk + 0][la] = vr.x; Rs[lk + 1][la] = vr.y; Rs[lk + 2][la] = vr.z; Rs[lk + 3][la] = vr.w;
        Ts[lk + 0][la] = vt.x; Ts[lk + 1][la] = vt.y; Ts[lk + 2][la] = vt.z; Ts[lk + 3][la] = vt.w;
        Cs[lk + 0][la] = vc.x; Cs[lk + 1][la] = vc.y; Cs[lk + 2][la] = vc.z; Cs[lk + 3][la] = vc.w;
        __syncthreads();

        #pragma unroll
        for (int kk = 0; kk < 16; kk++) {
            float4 r = *(const float4*)&Rs[kk][ty * 4];
            float4 t = *(const float4*)&Ts[kk][ty * 4];
            float4 c = *(const float4*)&Cs[kk][tx * 4];
            float rr[4] = { r.x, r.y, r.z, r.w };
            float tt[4] = { t.x, t.y, t.z, t.w };
            float cc[4] = { c.x, c.y, c.z, c.w };
            #pragma unroll
            for (int i = 0; i < 4; i++)
                #pragma unroll
                for (int jj = 0; jj < 4; jj++) {
                    acc1[i][jj] = fmaf(rr[i], cc[jj], acc1[i][jj]);
                    acc2[i][jj] = fmaf(tt[i], cc[jj], acc2[i][jj]);
                }
        }
    }

    int aRow = aBase + ty * 4;
    int bCol = bBase + tx * 4;
    #pragma unroll
    for (int i = 0; i < 4; i++)
        #pragma unroll
        for (int jj = 0; jj < 4; jj++) {
            g_S1p[ks * PAIRS + (aRow + i) * NCLS + (bCol + jj)] = acc1[i][jj];
            g_S2p[ks * PAIRS + (aRow + i) * NCLS + (bCol + jj)] = acc2[i][jj];
        }
}

// ---------------- kernel 5: per-pair loss + block reduce ----------------
// grid: 128 blocks (a) x 128 threads (b)
__global__ void k_pair() {
    int a = blockIdx.x, b = threadIdx.x;

    float dot1 = 0.f, dot2 = 0.f;
    #pragma unroll
    for (int s = 0; s < KSPLIT; s++) {
        dot1 += g_S1p[s * PAIRS + a * NCLS + b];
        dot2 += g_S2p[s * PAIRS + a * NCLS + b];
    }
    float nRa = g_nR[a*4+0] + g_nR[a*4+1] + g_nR[a*4+2] + g_nR[a*4+3];
    float nTa = g_nT[a*4+0] + g_nT[a*4+1] + g_nT[a*4+2] + g_nT[a*4+3];
    float nCb = g_nC[b*4+0] + g_nC[b*4+1] + g_nC[b*4+2] + g_nC[b*4+3];

    // matrix 1 (modal1 vs centers)
    float sq1 = fmaxf(nRa + nCb - 2.f * dot1, 1e-12f);
    float d1  = sqrtf(sq1);
    float dd1 = sqrtf(d1 + 1e-10f);
    float h1  = fmaxf(0.5f - dd1, 0.f);
    float t1  = (a == b) ? sq1 : h1 * h1;

    // matrix 2 (modal2 vs centers)
    float sq2 = fmaxf(nTa + nCb - 2.f * dot2, 1e-12f);
    float d2  = sqrtf(sq2);
    float dd2 = sqrtf(d2 + 1e-10f);
    float h2  = fmaxf(0.5f - dd2, 0.f);
    float t2  = (a == b) ? sq2 : h2 * h2;

    double w = (double)g_cnt[a] * (double)g_cnt[b];
    double v = w * ((double)t1 + (double)t2);

    #pragma unroll
    for (int o = 16; o > 0; o >>= 1)
        v += __shfl_down_sync(0xffffffffu, v, o);
    __shared__ double shd[4];
    int warp = threadIdx.x >> 5, lane = threadIdx.x & 31;
    if (lane == 0) shd[warp] = v;
    __syncthreads();
    if (threadIdx.x == 0)
        g_blk[a] = shd[0] + shd[1] + shd[2] + shd[3];
}

// ---------------- kernel 6: final scalar ----------------
__global__ void k_final(float* __restrict__ out, int out_n) {
    double v = g_blk[threadIdx.x];   // 128 threads
    #pragma unroll
    for (int o = 16; o > 0; o >>= 1)
        v += __shfl_down_sync(0xffffffffu, v, o);
    __shared__ double shd[4];
    __shared__ double total;
    int warp = threadIdx.x >> 5, lane = threadIdx.x & 31;
    if (lane == 0) shd[warp] = v;
    __syncthreads();
    if (threadIdx.x == 0)
        total = (shd[0] + shd[1] + shd[2] + shd[3]) / (4096.0 * 4096.0);
    __syncthreads();
    float r = (float)total;
    for (int i = threadIdx.x; i < out_n; i += blockDim.x) out[i] = r;
}

extern "C" void kernel_launch(void* const* d_in, const int* in_sizes, int n_in,
                              void* d_out, int out_size) {
    const float* m1 = (const float*)d_in[0];
    const float* m2 = (const float*)d_in[1];
    const int*   tg = (const int*)d_in[2];
    float* out = (float*)d_out;

    k_zero<<<1, 128>>>();
    k_scatter<<<16, 256>>>(tg);
    k_means<<<NCLS * 4, 128>>>(m1, m2);
    k_gemm<<<KSPLIT * 4, 256>>>();
    k_pair<<<NCLS, NCLS>>>();
    k_final<<<1, 128>>>(out, out_size);
}

// round 3
// speedup vs baseline: 1.0789x; 1.0789x over previous
#include <cuda_runtime.h>

#define NCLS   128
#define DIM    2048
#define NPTS   4096
#define CAP    512
#define KSPLIT 64
#define KCHUNK (DIM / KSPLIT)   // 32
#define PAIRS  (NCLS * NCLS)

// ---------------- scratch (device globals: no allocation allowed) ----------------
__device__ int    g_cnt[NCLS];
__device__ int    g_idx[NCLS * CAP];
__device__ float  g_meanR[NCLS * DIM];
__device__ float  g_meanT[NCLS * DIM];
__device__ float  g_meanC[NCLS * DIM];
__device__ float  g_nR[NCLS * 4];
__device__ float  g_nT[NCLS * 4];
__device__ float  g_nC[NCLS * 4];
__device__ float  g_S1p[KSPLIT * PAIRS];   // split-K partial dots meanR . meanC
__device__ float  g_S2p[KSPLIT * PAIRS];   // split-K partial dots meanT . meanC
__device__ double g_blk[NCLS];

// ---------------- kernel 1: zero counters ----------------
__global__ void k_zero() {
    int t = threadIdx.x;
    if (t < NCLS) g_cnt[t] = 0;
}

// ---------------- kernel 2: scatter row indices by class ----------------
__global__ void k_scatter(const int* __restrict__ tg) {
    int i = blockIdx.x * blockDim.x + threadIdx.x;
    if (i < NPTS) {
        int t = tg[i];
        int p = atomicAdd(&g_cnt[t], 1);
        g_idx[t * CAP + p] = i;
    }
}

// ---------------- kernel 3: segment means + norms ----------------
// grid: 512 blocks = 128 classes x 4 column chunks; 128 threads; thread owns 1 float4
// index list staged in smem; 4-row unroll for MLP=8
__global__ void k_means(const float* __restrict__ m1, const float* __restrict__ m2) {
    int c  = blockIdx.x >> 2;
    int ch = blockIdx.x & 3;
    int off = ch * 512 + threadIdx.x * 4;

    __shared__ int sidx[CAP];
    int n = g_cnt[c];
    for (int j = threadIdx.x; j < n; j += 128)
        sidx[j] = g_idx[c * CAP + j] * DIM;
    __syncthreads();

    float4 aR = make_float4(0.f, 0.f, 0.f, 0.f);
    float4 aT = make_float4(0.f, 0.f, 0.f, 0.f);

    int j = 0;
    for (; j + 4 <= n; j += 4) {
        int i0 = sidx[j], i1 = sidx[j + 1], i2 = sidx[j + 2], i3 = sidx[j + 3];
        float4 r0 = *(const float4*)(m1 + i0 + off);
        float4 r1 = *(const float4*)(m1 + i1 + off);
        float4 r2 = *(const float4*)(m1 + i2 + off);
        float4 r3 = *(const float4*)(m1 + i3 + off);
        float4 t0 = *(const float4*)(m2 + i0 + off);
        float4 t1 = *(const float4*)(m2 + i1 + off);
        float4 t2 = *(const float4*)(m2 + i2 + off);
        float4 t3 = *(const float4*)(m2 + i3 + off);
        aR.x += (r0.x + r1.x) + (r2.x + r3.x);
        aR.y += (r0.y + r1.y) + (r2.y + r3.y);
        aR.z += (r0.z + r1.z) + (r2.z + r3.z);
        aR.w += (r0.w + r1.w) + (r2.w + r3.w);
        aT.x += (t0.x + t1.x) + (t2.x + t3.x);
        aT.y += (t0.y + t1.y) + (t2.y + t3.y);
        aT.z += (t0.z + t1.z) + (t2.z + t3.z);
        aT.w += (t0.w + t1.w) + (t2.w + t3.w);
    }
    for (; j < n; j++) {
        int i0 = sidx[j];
        float4 r0 = *(const float4*)(m1 + i0 + off);
        float4 t0 = *(const float4*)(m2 + i0 + off);
        aR.x += r0.x; aR.y += r0.y; aR.z += r0.z; aR.w += r0.w;
        aT.x += t0.x; aT.y += t0.y; aT.z += t0.z; aT.w += t0.w;
    }

    float inv = 1.f / (float)max(n, 1);
    float4 mR = make_float4(aR.x * inv, aR.y * inv, aR.z * inv, aR.w * inv);
    float4 mT = make_float4(aT.x * inv, aT.y * inv, aT.z * inv, aT.w * inv);
    float4 mC = make_float4(0.5f * (mR.x + mT.x), 0.5f * (mR.y + mT.y),
                            0.5f * (mR.z + mT.z), 0.5f * (mR.w + mT.w));

    int wb = c * DIM + off;
    *(float4*)(g_meanR + wb) = mR;
    *(float4*)(g_meanT + wb) = mT;
    *(float4*)(g_meanC + wb) = mC;

    float sR = mR.x*mR.x + mR.y*mR.y + mR.z*mR.z + mR.w*mR.w;
    float sT = mT.x*mT.x + mT.y*mT.y + mT.z*mT.z + mT.w*mT.w;
    float sC = mC.x*mC.x + mC.y*mC.y + mC.z*mC.z + mC.w*mC.w;

    #pragma unroll
    for (int o = 16; o > 0; o >>= 1) {
        sR += __shfl_down_sync(0xffffffffu, sR, o);
        sT += __shfl_down_sync(0xffffffffu, sT, o);
        sC += __shfl_down_sync(0xffffffffu, sC, o);
    }
    __shared__ float shn[3][4];
    int warp = threadIdx.x >> 5, lane = threadIdx.x & 31;
    if (lane == 0) { shn[0][warp] = sR; shn[1][warp] = sT; shn[2][warp] = sC; }
    __syncthreads();
    if (threadIdx.x == 0) {
        g_nR[c * 4 + ch] = shn[0][0] + shn[0][1] + shn[0][2] + shn[0][3];
        g_nT[c * 4 + ch] = shn[1][0] + shn[1][1] + shn[1][2] + shn[1][3];
        g_nC[c * 4 + ch] = shn[2][0] + shn[2][1] + shn[2][2] + shn[2][3];
    }
}

// ---------------- kernel 4: split-K GEMMs S1 = R*C^T, S2 = T*C^T ----------------
// grid: 256 blocks = 64 K-splits x (2x2 output tiles of 64x64); 256 threads; 4x4 reg tile
__global__ void k_gemm() {
    __shared__ float Rs[16][68];
    __shared__ float Ts[16][68];
    __shared__ float Cs[16][68];

    int bx = blockIdx.x;
    int ks = bx >> 2;
    int tile = bx & 3;
    int aBase = (tile >> 1) * 64;
    int bBase = (tile & 1) * 64;

    int tid = threadIdx.x;
    int tx = tid & 15;
    int ty = tid >> 4;

    int la = tid >> 2;
    int lk = (tid & 3) * 4;

    float acc1[4][4] = {};
    float acc2[4][4] = {};

    int k0 = ks * KCHUNK;
    for (int kb = k0; kb < k0 + KCHUNK; kb += 16) {
        float4 vr = *(const float4*)(g_meanR + (aBase + la) * DIM + kb + lk);
        float4 vt = *(const float4*)(g_meanT + (aBase + la) * DIM + kb + lk);
        float4 vc = *(const float4*)(g_meanC + (bBase + la) * DIM + kb + lk);
        __syncthreads();
        Rs[lk + 0][la] = vr.x; Rs[lk + 1][la] = vr.y; Rs[lk + 2][la] = vr.z; Rs[lk + 3][la] = vr.w;
        Ts[lk + 0][la] = vt.x; Ts[lk + 1][la] = vt.y; Ts[lk + 2][la] = vt.z; Ts[lk + 3][la] = vt.w;
        Cs[lk + 0][la] = vc.x; Cs[lk + 1][la] = vc.y; Cs[lk + 2][la] = vc.z; Cs[lk + 3][la] = vc.w;
        __syncthreads();

        #pragma unroll
        for (int kk = 0; kk < 16; kk++) {
            float4 r = *(const float4*)&Rs[kk][ty * 4];
            float4 t = *(const float4*)&Ts[kk][ty * 4];
            float4 c = *(const float4*)&Cs[kk][tx * 4];
            float rr[4] = { r.x, r.y, r.z, r.w };
            float tt[4] = { t.x, t.y, t.z, t.w };
            float cc[4] = { c.x, c.y, c.z, c.w };
            #pragma unroll
            for (int i = 0; i < 4; i++)
                #pragma unroll
                for (int jj = 0; jj < 4; jj++) {
                    acc1[i][jj] = fmaf(rr[i], cc[jj], acc1[i][jj]);
                    acc2[i][jj] = fmaf(tt[i], cc[jj], acc2[i][jj]);
                }
        }
    }

    int aRow = aBase + ty * 4;
    int bCol = bBase + tx * 4;
    #pragma unroll
    for (int i = 0; i < 4; i++)
        #pragma unroll
        for (int jj = 0; jj < 4; jj++) {
            g_S1p[ks * PAIRS + (aRow + i) * NCLS + (bCol + jj)] = acc1[i][jj];
            g_S2p[ks * PAIRS + (aRow + i) * NCLS + (bCol + jj)] = acc2[i][jj];
        }
}

// ---------------- kernel 5: per-pair loss + block reduce ----------------
__global__ void k_pair() {
    int a = blockIdx.x, b = threadIdx.x;

    float dot1 = 0.f, dot2 = 0.f;
    #pragma unroll
    for (int s = 0; s < KSPLIT; s++) {
        dot1 += g_S1p[s * PAIRS + a * NCLS + b];
        dot2 += g_S2p[s * PAIRS + a * NCLS + b];
    }
    float nRa = g_nR[a*4+0] + g_nR[a*4+1] + g_nR[a*4+2] + g_nR[a*4+3];
    float nTa = g_nT[a*4+0] + g_nT[a*4+1] + g_nT[a*4+2] + g_nT[a*4+3];
    float nCb = g_nC[b*4+0] + g_nC[b*4+1] + g_nC[b*4+2] + g_nC[b*4+3];

    float sq1 = fmaxf(nRa + nCb - 2.f * dot1, 1e-12f);
    float d1  = sqrtf(sq1);
    float dd1 = sqrtf(d1 + 1e-10f);
    float h1  = fmaxf(0.5f - dd1, 0.f);
    float t1  = (a == b) ? sq1 : h1 * h1;

    float sq2 = fmaxf(nTa + nCb - 2.f * dot2, 1e-12f);
    float d2  = sqrtf(sq2);
    float dd2 = sqrtf(d2 + 1e-10f);
    float h2  = fmaxf(0.5f - dd2, 0.f);
    float t2  = (a == b) ? sq2 : h2 * h2;

    double w = (double)g_cnt[a] * (double)g_cnt[b];
    double v = w * ((double)t1 + (double)t2);

    #pragma unroll
    for (int o = 16; o > 0; o >>= 1)
        v += __shfl_down_sync(0xffffffffu, v, o);
    __shared__ double shd[4];
    int warp = threadIdx.x >> 5, lane = threadIdx.x & 31;
    if (lane == 0) shd[warp] = v;
    __syncthreads();
    if (threadIdx.x == 0)
        g_blk[a] = shd[0] + shd[1] + shd[2] + shd[3];
}

// ---------------- kernel 6: final scalar ----------------
__global__ void k_final(float* __restrict__ out, int out_n) {
    double v = g_blk[threadIdx.x];
    #pragma unroll
    for (int o = 16; o > 0; o >>= 1)
        v += __shfl_down_sync(0xffffffffu, v, o);
    __shared__ double shd[4];
    __shared__ double total;
    int warp = threadIdx.x >> 5, lane = threadIdx.x & 31;
    if (lane == 0) shd[warp] = v;
    __syncthreads();
    if (threadIdx.x == 0)
        total = (shd[0] + shd[1] + shd[2] + shd[3]) / (4096.0 * 4096.0);
    __syncthreads();
    float r = (float)total;
    for (int i = threadIdx.x; i < out_n; i += blockDim.x) out[i] = r;
}

extern "C" void kernel_launch(void* const* d_in, const int* in_sizes, int n_in,
                              void* d_out, int out_size) {
    const float* m1 = (const float*)d_in[0];
    const float* m2 = (const float*)d_in[1];
    const int*   tg = (const int*)d_in[2];
    float* out = (float*)d_out;

    k_zero<<<1, 128>>>();
    k_scatter<<<16, 256>>>(tg);
    k_means<<<NCLS * 4, 128>>>(m1, m2);
    k_gemm<<<KSPLIT * 4, 256>>>();
    k_pair<<<NCLS, NCLS>>>();
    k_final<<<1, 128>>>(out, out_size);
}